// round 11
// baseline (speedup 1.0000x reference)
#include <cuda_runtime.h>
#include <mma.h>
#include <math.h>
#include <stdint.h>

using namespace nvcuda;

#define B_ 4
#define L_ 4096
#define D_ 1024
#define R_ 16
#define PLU_ 120
#define PLUP_ 128
#define GEO_ 256
#define BL_ 16384
#define MROWS_ (6 * BL_)
#define EPS_ 1e-6f

// Scratch (static device globals: allocation-free)
__device__ float d_Z[BL_ * R_];                  // (B*L, 16)
__device__ float d_S[BL_ * GEO_];                // (B*L, 256)
__device__ float d_P[(size_t)MROWS_ * PLUP_];    // plucker rows (cols 120..127 = 0)
__device__ float d_U[(size_t)MROWS_ * GEO_];     // RAW P@g1w accum (bias/gelu in reduce)
__device__ float d_G[(size_t)BL_ * D_];          // g (raw fp32)
__device__ float d_G1p[PLUP_ * GEO_];            // g1_w padded to 128 rows

__constant__ int c_off[6] = {1, 2, 4, 8, 16, 32};

__device__ __forceinline__ uint32_t smem_u32(const void* p) {
    uint32_t a;
    asm("{ .reg .u64 t; cvta.to.shared.u64 t, %1; cvt.u32.u64 %0, t; }"
        : "=r"(a) : "l"(p));
    return a;
}
__device__ __forceinline__ void cp16(uint32_t s, const void* g) {
    asm volatile("cp.async.cg.shared.global [%0], [%1], 16;" :: "r"(s), "l"(g));
}
__device__ __forceinline__ void cp_commit() { asm volatile("cp.async.commit_group;"); }
template <int N>
__device__ __forceinline__ void cp_wait() {
    asm volatile("cp.async.wait_group %0;" :: "n"(N));
}
__device__ __forceinline__ float gelu_exact(float x) {
    return 0.5f * x * (1.f + erff(x * 0.7071067811865476f));
}
__device__ __forceinline__ int count_of(int l) {
    return (l >= 1) + (l >= 2) + (l >= 4) + (l >= 8) + (l >= 16) + (l >= 32);
}

// ---------------- z = h @ red_w + red_b ----------------
__global__ void k_z(const float* __restrict__ h,
                    const float* __restrict__ rw,
                    const float* __restrict__ rb) {
    int t = blockIdx.x * 16 + (threadIdx.x >> 4);
    int r = threadIdx.x & 15;
    const float* hrow = h + (size_t)t * D_;
    float acc = rb[r];
    #pragma unroll 4
    for (int d = 0; d < D_; d += 4) {
        float4 hv = *reinterpret_cast<const float4*>(hrow + d);
        acc += hv.x * rw[(d + 0) * R_ + r];
        acc += hv.y * rw[(d + 1) * R_ + r];
        acc += hv.z * rw[(d + 2) * R_ + r];
        acc += hv.w * rw[(d + 3) * R_ + r];
    }
    d_Z[t * R_ + r] = acc;
}

// ---------------- pad g1_w 120 -> 128 rows ----------------
__global__ void k_pad_g1(const float* __restrict__ g1w) {
    int fid = blockIdx.x * 256 + threadIdx.x;   // 8192 float4s
    int row = fid >> 6;
    int c = (fid & 63) * 4;
    float4 v = make_float4(0.f, 0.f, 0.f, 0.f);
    if (row < PLU_)
        v = *reinterpret_cast<const float4*>(g1w + (size_t)row * GEO_ + c);
    *reinterpret_cast<float4*>(d_G1p + (size_t)row * GEO_ + c) = v;
}

// ---------------- plucker rows: d_P[di*BL + t][0:128] ----------------
// All shuffles warp-uniform.
__global__ void k_plucker() {
    int wid = threadIdx.x >> 5, lane = threadIdx.x & 31;
    int ridx = blockIdx.x * 8 + wid;
    int di = ridx / BL_;
    int t = ridx - di * BL_;
    int l = t & (L_ - 1);
    int delta = c_off[di];
    float* dst = d_P + (size_t)ridx * PLUP_;
    if (l < delta) {                       // warp-uniform branch
        #pragma unroll
        for (int q = 0; q < 4; ++q) dst[lane + q * 32] = 0.f;
        return;
    }
    int tp = t - delta;
    float w = (lane < 16) ? d_Z[tp * R_ + lane] : d_Z[t * R_ + lane - 16];
    float p[4];
    float sq = 0.f;
    #pragma unroll
    for (int q = 0; q < 4; ++q) {
        int k = lane + q * 32;
        int kc = (k < PLU_) ? k : 0;
        int kk = kc, i = 0, len = R_ - 1;
        while (kk >= len) { kk -= len; i++; len--; }
        int j = i + 1 + kk;
        float ui = __shfl_sync(0xffffffffu, w, i);
        float uj = __shfl_sync(0xffffffffu, w, j);
        float vi = __shfl_sync(0xffffffffu, w, 16 + i);
        float vj = __shfl_sync(0xffffffffu, w, 16 + j);
        float val = (k < PLU_) ? (ui * vj - uj * vi) : 0.f;
        p[q] = val;
        sq += val * val;
    }
    #pragma unroll
    for (int o = 16; o > 0; o >>= 1) sq += __shfl_xor_sync(0xffffffffu, sq, o);
    float inv = 1.f / fmaxf(sqrtf(sq), EPS_);
    #pragma unroll
    for (int q = 0; q < 4; ++q) dst[lane + q * 32] = p[q] * inv;
}

// -------- reduce: d_S = (sum masked gelu(d_U + g1b))/cnt ----------------
__global__ void k_reduce(const float* __restrict__ g1b) {
    int fid = blockIdx.x * 256 + threadIdx.x;   // BL*GEO/4 float4s
    int t = fid >> 6;
    int c = (fid & 63) * 4;
    int l = t & (L_ - 1);
    float4 bb = *reinterpret_cast<const float4*>(g1b + c);
    float4 s = make_float4(0.f, 0.f, 0.f, 0.f);
    #pragma unroll
    for (int di = 0; di < 6; ++di) {
        if (l >= c_off[di]) {
            float4 u = *reinterpret_cast<const float4*>(
                d_U + (size_t)(di * BL_ + t) * GEO_ + c);
            s.x += gelu_exact(u.x + bb.x);
            s.y += gelu_exact(u.y + bb.y);
            s.z += gelu_exact(u.z + bb.z);
            s.w += gelu_exact(u.w + bb.w);
        }
    }
    int cnt = count_of(l);
    float sc = cnt > 0 ? 1.f / (float)cnt : 0.f;
    s.x *= sc; s.y *= sc; s.z *= sc; s.w *= sc;
    *reinterpret_cast<float4*>(d_S + (size_t)t * GEO_ + c) = s;
}

// ------- wmma tf32 GEMM, block 128x256, warp 64x64, BK=32, 2-stage -------
// MODE 0: A=d_S (K=256),  B=g2_w:   d_G = cnt>0 ? acc + g2b : 0
// MODE 1: A=[h|d_G] (K=2048), B=gate_w: out = sig(acc+gb)*h + (1-sig)*d_G
// MODE 2: A=d_P (K=128),  B=d_G1p (NG=256): d_U = raw acc (direct global store)
#define LDA 36
#define LDB 260
#define EPLD 36
#define STAGE_F (128 * LDA + 32 * LDB)     // 4608 + 8320 = 12928 floats
#define SMEM_GEMM (2 * STAGE_F * 4)        // 103424 bytes

template <int MODE>
__global__ void __launch_bounds__(256) k_gemm(const float* __restrict__ hA,
                                              const float* __restrict__ Bw,
                                              const float* __restrict__ bias,
                                              float* __restrict__ out) {
    extern __shared__ __align__(128) float sm[];
    constexpr int KTOT = (MODE == 1) ? 2 * D_ : (MODE == 0 ? GEO_ : PLUP_);
    constexpr int NG = (MODE == 2) ? GEO_ : D_;
    constexpr int NIT = KTOT / 32;

    const int tid = threadIdx.x;
    const int wid = tid >> 5, lane = tid & 31;
    const int wm = wid >> 2, wn = wid & 3;    // 2 x 4 warp grid, 64x64 per warp
    const int m0 = blockIdx.y * 128;
    const int n0 = blockIdx.x * 256;
    const uint32_t smb = smem_u32(sm);

    wmma::fragment<wmma::accumulator, 16, 16, 8, float> acc[4][4];
    #pragma unroll
    for (int i = 0; i < 4; ++i)
        #pragma unroll
        for (int j = 0; j < 4; ++j) wmma::fill_fragment(acc[i][j], 0.f);

    auto load_async = [&](int it, int s) {
        const int k0 = it * 32;
        const uint32_t aoff = s * STAGE_F;
        const uint32_t boff = s * STAGE_F + 128 * LDA;
        // A: 128 rows x 32 floats -> 1024 float4, 4 per thread
        #pragma unroll
        for (int p = 0; p < 4; ++p) {
            int idx = tid + p * 256;
            int row = idx >> 3, c4 = idx & 7;
            const float* gp;
            if (MODE == 1)
                gp = (k0 < D_) ? hA + (size_t)(m0 + row) * D_ + k0 + c4 * 4
                               : d_G + (size_t)(m0 + row) * D_ + (k0 - D_) + c4 * 4;
            else if (MODE == 0)
                gp = d_S + (size_t)(m0 + row) * GEO_ + k0 + c4 * 4;
            else
                gp = d_P + (size_t)(m0 + row) * PLUP_ + k0 + c4 * 4;
            cp16(smb + (aoff + row * LDA + c4 * 4) * 4, gp);
        }
        // B: 32 rows x 256 floats -> 2048 float4, 8 per thread
        #pragma unroll
        for (int p = 0; p < 8; ++p) {
            int idx = tid + p * 256;
            int row = idx >> 6, c4 = idx & 63;
            cp16(smb + (boff + row * LDB + c4 * 4) * 4,
                 Bw + (size_t)(k0 + row) * NG + n0 + c4 * 4);
        }
        cp_commit();
    };

    auto compute = [&](int s) {
        const float* As = sm + s * STAGE_F;
        const float* Bs = sm + s * STAGE_F + 128 * LDA;
        #pragma unroll
        for (int ks = 0; ks < 4; ++ks) {
            wmma::fragment<wmma::matrix_a, 16, 16, 8, wmma::precision::tf32,
                           wmma::row_major> a[4];
            wmma::fragment<wmma::matrix_b, 16, 16, 8, wmma::precision::tf32,
                           wmma::row_major> b[4];
            #pragma unroll
            for (int i = 0; i < 4; ++i)
                wmma::load_matrix_sync(a[i], As + (wm * 64 + i * 16) * LDA + ks * 8, LDA);
            #pragma unroll
            for (int j = 0; j < 4; ++j)
                wmma::load_matrix_sync(b[j], Bs + ks * 8 * LDB + wn * 64 + j * 16, LDB);
            #pragma unroll
            for (int i = 0; i < 4; ++i)
                #pragma unroll
                for (int j = 0; j < 4; ++j)
                    wmma::mma_sync(acc[i][j], a[i], b[j], acc[i][j]);
        }
    };

    load_async(0, 0);
    for (int it = 0; it < NIT; ++it) {
        int cur = it & 1;
        if (it + 1 < NIT) {
            load_async(it + 1, 1 - cur);
            cp_wait<1>();
        } else {
            cp_wait<0>();
        }
        __syncthreads();
        compute(cur);
        __syncthreads();
    }

    if (MODE == 2) {
        // Direct global store of raw accumulators (bias/gelu folded into k_reduce)
        #pragma unroll
        for (int i = 0; i < 4; ++i)
            #pragma unroll
            for (int j = 0; j < 4; ++j)
                wmma::store_matrix_sync(
                    out + (size_t)(m0 + wm * 64 + i * 16) * GEO_ + wn * 64 + j * 16,
                    acc[i][j], GEO_, wmma::mem_row_major);
        return;
    }

    // Staged epilogue: per-warp private 64x32 buffer (stride EPLD), two N-halves
    float* ep = sm + wid * (64 * EPLD);   // 8 * 2304 floats = 73.7KB < 103.4KB
    #pragma unroll
    for (int half = 0; half < 2; ++half) {
        __syncwarp();
        #pragma unroll
        for (int i = 0; i < 4; ++i)
            #pragma unroll
            for (int jj = 0; jj < 2; ++jj)
                wmma::store_matrix_sync(ep + (i * 16) * EPLD + jj * 16,
                                        acc[i][half * 2 + jj], EPLD,
                                        wmma::mem_row_major);
        __syncwarp();
        #pragma unroll
        for (int rr = 0; rr < 2; ++rr) {
            int r = lane + rr * 32;
            int m = m0 + wm * 64 + r;
            int nbase = n0 + wn * 64 + half * 32;
            const float* row = ep + r * EPLD;
            if (MODE == 1) {
                const float* hp = hA + (size_t)m * D_ + nbase;
                const float* gp = d_G + (size_t)m * D_ + nbase;
                float* op = out + (size_t)m * D_ + nbase;
                #pragma unroll
                for (int c4 = 0; c4 < 8; ++c4) {
                    float4 v = *reinterpret_cast<const float4*>(row + c4 * 4);
                    float4 bb = *reinterpret_cast<const float4*>(bias + nbase + c4 * 4);
                    float4 hv = *reinterpret_cast<const float4*>(hp + c4 * 4);
                    float4 gv = *reinterpret_cast<const float4*>(gp + c4 * 4);
                    float pr[4] = {v.x + bb.x, v.y + bb.y, v.z + bb.z, v.w + bb.w};
                    float hr[4] = {hv.x, hv.y, hv.z, hv.w};
                    float gr[4] = {gv.x, gv.y, gv.z, gv.w};
                    float4 o;
                    float* opv = &o.x;
                    #pragma unroll
                    for (int j = 0; j < 4; ++j) {
                        float alpha = 1.f / (1.f + expf(-pr[j]));
                        opv[j] = alpha * hr[j] + (1.f - alpha) * gr[j];
                    }
                    *reinterpret_cast<float4*>(op + c4 * 4) = o;
                }
            } else {
                int l = m & (L_ - 1);
                bool on = count_of(l) > 0;
                float* gp = d_G + (size_t)m * D_ + nbase;
                #pragma unroll
                for (int c4 = 0; c4 < 8; ++c4) {
                    float4 v = *reinterpret_cast<const float4*>(row + c4 * 4);
                    float4 bb = *reinterpret_cast<const float4*>(bias + nbase + c4 * 4);
                    float4 o;
                    o.x = on ? v.x + bb.x : 0.f;
                    o.y = on ? v.y + bb.y : 0.f;
                    o.z = on ? v.z + bb.z : 0.f;
                    o.w = on ? v.w + bb.w : 0.f;
                    *reinterpret_cast<float4*>(gp + c4 * 4) = o;
                }
            }
        }
    }
}

extern "C" void kernel_launch(void* const* d_in, const int* in_sizes, int n_in,
                              void* d_out, int out_size) {
    const float* h   = (const float*)d_in[0];
    const float* rw  = (const float*)d_in[1];
    const float* rb  = (const float*)d_in[2];
    const float* g1w = (const float*)d_in[3];
    const float* g1b = (const float*)d_in[4];
    const float* g2w = (const float*)d_in[5];
    const float* g2b = (const float*)d_in[6];
    const float* gw  = (const float*)d_in[7];
    const float* gb  = (const float*)d_in[8];
    float* out = (float*)d_out;
    (void)in_sizes; (void)n_in; (void)out_size;

    cudaFuncSetAttribute(k_gemm<0>, cudaFuncAttributeMaxDynamicSharedMemorySize, SMEM_GEMM);
    cudaFuncSetAttribute(k_gemm<1>, cudaFuncAttributeMaxDynamicSharedMemorySize, SMEM_GEMM);
    cudaFuncSetAttribute(k_gemm<2>, cudaFuncAttributeMaxDynamicSharedMemorySize, SMEM_GEMM);

    float *pP, *pU, *pS, *pG1;
    cudaGetSymbolAddress((void**)&pP, d_P);
    cudaGetSymbolAddress((void**)&pU, d_U);
    cudaGetSymbolAddress((void**)&pS, d_S);
    cudaGetSymbolAddress((void**)&pG1, d_G1p);

    k_pad_g1<<<PLUP_ * GEO_ / 1024, 256>>>(g1w);
    k_z<<<BL_ / 16, 256>>>(h, rw, rb);

    // geometry path
    k_plucker<<<MROWS_ / 8, 256>>>();
    k_gemm<2><<<dim3(1, MROWS_ / 128), 256, SMEM_GEMM>>>(pP, pG1, nullptr, pU);
    k_reduce<<<BL_ * GEO_ / 1024, 256>>>(g1b);

    // g = S @ g2_w + b -> d_G
    k_gemm<0><<<dim3(D_ / 256, BL_ / 128), 256, SMEM_GEMM>>>(
        pS, g2w, g2b, nullptr);

    // gated output
    k_gemm<1><<<dim3(D_ / 256, BL_ / 128), 256, SMEM_GEMM>>>(
        h, gw, gb, out);
}

// round 12
// speedup vs baseline: 1.0410x; 1.0410x over previous
#include <cuda_runtime.h>
#include <mma.h>
#include <math.h>
#include <stdint.h>

using namespace nvcuda;

#define B_ 4
#define L_ 4096
#define D_ 1024
#define R_ 16
#define PLU_ 120
#define PLUP_ 128
#define GEO_ 256
#define BL_ 16384
#define MROWS_ (6 * BL_)
#define EPS_ 1e-6f

// Scratch (static device globals: allocation-free)
__device__ float d_Z[BL_ * R_];                  // (B*L, 16)
__device__ float d_S[BL_ * GEO_];                // (B*L, 256)
__device__ float d_P[(size_t)MROWS_ * PLUP_];    // plucker rows (cols 120..127 = 0)
__device__ float d_U[(size_t)MROWS_ * GEO_];     // RAW P@g1w accum (bias/gelu in reduce)
__device__ float d_G[(size_t)BL_ * D_];          // g (raw fp32)
__device__ float d_G1p[PLUP_ * GEO_];            // g1_w padded to 128 rows

__constant__ int c_off[6] = {1, 2, 4, 8, 16, 32};

__device__ __forceinline__ uint32_t smem_u32(const void* p) {
    uint32_t a;
    asm("{ .reg .u64 t; cvta.to.shared.u64 t, %1; cvt.u32.u64 %0, t; }"
        : "=r"(a) : "l"(p));
    return a;
}
__device__ __forceinline__ void cp16(uint32_t s, const void* g) {
    asm volatile("cp.async.cg.shared.global [%0], [%1], 16;" :: "r"(s), "l"(g));
}
__device__ __forceinline__ void cp_commit() { asm volatile("cp.async.commit_group;"); }
template <int N>
__device__ __forceinline__ void cp_wait() {
    asm volatile("cp.async.wait_group %0;" :: "n"(N));
}
__device__ __forceinline__ float gelu_exact(float x) {
    return 0.5f * x * (1.f + erff(x * 0.7071067811865476f));
}
__device__ __forceinline__ int count_of(int l) {
    return (l >= 1) + (l >= 2) + (l >= 4) + (l >= 8) + (l >= 16) + (l >= 32);
}

// ---------------- z = h @ red_w + red_b ----------------
__global__ void k_z(const float* __restrict__ h,
                    const float* __restrict__ rw,
                    const float* __restrict__ rb) {
    int t = blockIdx.x * 16 + (threadIdx.x >> 4);
    int r = threadIdx.x & 15;
    const float* hrow = h + (size_t)t * D_;
    float acc = rb[r];
    #pragma unroll 4
    for (int d = 0; d < D_; d += 4) {
        float4 hv = *reinterpret_cast<const float4*>(hrow + d);
        acc += hv.x * rw[(d + 0) * R_ + r];
        acc += hv.y * rw[(d + 1) * R_ + r];
        acc += hv.z * rw[(d + 2) * R_ + r];
        acc += hv.w * rw[(d + 3) * R_ + r];
    }
    d_Z[t * R_ + r] = acc;
}

// ---------------- pad g1_w 120 -> 128 rows ----------------
__global__ void k_pad_g1(const float* __restrict__ g1w) {
    int fid = blockIdx.x * 256 + threadIdx.x;   // 8192 float4s
    int row = fid >> 6;
    int c = (fid & 63) * 4;
    float4 v = make_float4(0.f, 0.f, 0.f, 0.f);
    if (row < PLU_)
        v = *reinterpret_cast<const float4*>(g1w + (size_t)row * GEO_ + c);
    *reinterpret_cast<float4*>(d_G1p + (size_t)row * GEO_ + c) = v;
}

// ---------------- plucker rows: d_P[di*BL + t][0:128] ----------------
// All shuffles warp-uniform.
__global__ void k_plucker() {
    int wid = threadIdx.x >> 5, lane = threadIdx.x & 31;
    int ridx = blockIdx.x * 8 + wid;
    int di = ridx / BL_;
    int t = ridx - di * BL_;
    int l = t & (L_ - 1);
    int delta = c_off[di];
    float* dst = d_P + (size_t)ridx * PLUP_;
    if (l < delta) {                       // warp-uniform branch
        #pragma unroll
        for (int q = 0; q < 4; ++q) dst[lane + q * 32] = 0.f;
        return;
    }
    int tp = t - delta;
    float w = (lane < 16) ? d_Z[tp * R_ + lane] : d_Z[t * R_ + lane - 16];
    float p[4];
    float sq = 0.f;
    #pragma unroll
    for (int q = 0; q < 4; ++q) {
        int k = lane + q * 32;
        int kc = (k < PLU_) ? k : 0;
        int kk = kc, i = 0, len = R_ - 1;
        while (kk >= len) { kk -= len; i++; len--; }
        int j = i + 1 + kk;
        float ui = __shfl_sync(0xffffffffu, w, i);
        float uj = __shfl_sync(0xffffffffu, w, j);
        float vi = __shfl_sync(0xffffffffu, w, 16 + i);
        float vj = __shfl_sync(0xffffffffu, w, 16 + j);
        float val = (k < PLU_) ? (ui * vj - uj * vi) : 0.f;
        p[q] = val;
        sq += val * val;
    }
    #pragma unroll
    for (int o = 16; o > 0; o >>= 1) sq += __shfl_xor_sync(0xffffffffu, sq, o);
    float inv = 1.f / fmaxf(sqrtf(sq), EPS_);
    #pragma unroll
    for (int q = 0; q < 4; ++q) dst[lane + q * 32] = p[q] * inv;
}

// -------- reduce: d_S = (sum masked gelu(d_U + g1b))/cnt ----------------
__global__ void k_reduce(const float* __restrict__ g1b) {
    int fid = blockIdx.x * 256 + threadIdx.x;   // BL*GEO/4 float4s
    int t = fid >> 6;
    int c = (fid & 63) * 4;
    int l = t & (L_ - 1);
    float4 bb = *reinterpret_cast<const float4*>(g1b + c);
    float4 s = make_float4(0.f, 0.f, 0.f, 0.f);
    #pragma unroll
    for (int di = 0; di < 6; ++di) {
        if (l >= c_off[di]) {
            float4 u = *reinterpret_cast<const float4*>(
                d_U + (size_t)(di * BL_ + t) * GEO_ + c);
            s.x += gelu_exact(u.x + bb.x);
            s.y += gelu_exact(u.y + bb.y);
            s.z += gelu_exact(u.z + bb.z);
            s.w += gelu_exact(u.w + bb.w);
        }
    }
    int cnt = count_of(l);
    float sc = cnt > 0 ? 1.f / (float)cnt : 0.f;
    s.x *= sc; s.y *= sc; s.z *= sc; s.w *= sc;
    *reinterpret_cast<float4*>(d_S + (size_t)t * GEO_ + c) = s;
}

// ===== k_gemm_big: MODE-2-only. block 128x256, warp 64x64, direct store =====
// A = d_P (K=128), B = d_G1p (N=256). out = raw accum -> d_U.
#define BLDA 36
#define BLDB 260
#define BSTAGE_F (128 * BLDA + 32 * BLDB)    // 12928 floats
#define SMEM_BIG (2 * BSTAGE_F * 4)          // 103424 bytes

__global__ void __launch_bounds__(256) k_gemm_big(const float* __restrict__ Aw,
                                                  const float* __restrict__ Bw,
                                                  float* __restrict__ out) {
    extern __shared__ __align__(128) float sm[];
    constexpr int NIT = PLUP_ / 32;

    const int tid = threadIdx.x;
    const int wid = tid >> 5;
    const int wm = wid >> 2, wn = wid & 3;    // 2 x 4 warp grid, 64x64 per warp
    const int m0 = blockIdx.y * 128;
    const uint32_t smb = smem_u32(sm);

    wmma::fragment<wmma::accumulator, 16, 16, 8, float> acc[4][4];
    #pragma unroll
    for (int i = 0; i < 4; ++i)
        #pragma unroll
        for (int j = 0; j < 4; ++j) wmma::fill_fragment(acc[i][j], 0.f);

    auto load_async = [&](int it, int s) {
        const int k0 = it * 32;
        const uint32_t aoff = s * BSTAGE_F;
        const uint32_t boff = s * BSTAGE_F + 128 * BLDA;
        #pragma unroll
        for (int p = 0; p < 4; ++p) {
            int idx = tid + p * 256;
            int row = idx >> 3, c4 = idx & 7;
            cp16(smb + (aoff + row * BLDA + c4 * 4) * 4,
                 Aw + (size_t)(m0 + row) * PLUP_ + k0 + c4 * 4);
        }
        #pragma unroll
        for (int p = 0; p < 8; ++p) {
            int idx = tid + p * 256;
            int row = idx >> 6, c4 = idx & 63;
            cp16(smb + (boff + row * BLDB + c4 * 4) * 4,
                 Bw + (size_t)(k0 + row) * GEO_ + c4 * 4);
        }
        cp_commit();
    };

    auto compute = [&](int s) {
        const float* As = sm + s * BSTAGE_F;
        const float* Bs = sm + s * BSTAGE_F + 128 * BLDA;
        #pragma unroll
        for (int ks = 0; ks < 4; ++ks) {
            wmma::fragment<wmma::matrix_a, 16, 16, 8, wmma::precision::tf32,
                           wmma::row_major> a[4];
            wmma::fragment<wmma::matrix_b, 16, 16, 8, wmma::precision::tf32,
                           wmma::row_major> b[4];
            #pragma unroll
            for (int i = 0; i < 4; ++i)
                wmma::load_matrix_sync(a[i], As + (wm * 64 + i * 16) * BLDA + ks * 8, BLDA);
            #pragma unroll
            for (int j = 0; j < 4; ++j)
                wmma::load_matrix_sync(b[j], Bs + ks * 8 * BLDB + wn * 64 + j * 16, BLDB);
            #pragma unroll
            for (int i = 0; i < 4; ++i)
                #pragma unroll
                for (int j = 0; j < 4; ++j)
                    wmma::mma_sync(acc[i][j], a[i], b[j], acc[i][j]);
        }
    };

    load_async(0, 0);
    for (int it = 0; it < NIT; ++it) {
        int cur = it & 1;
        if (it + 1 < NIT) {
            load_async(it + 1, 1 - cur);
            cp_wait<1>();
        } else {
            cp_wait<0>();
        }
        __syncthreads();
        compute(cur);
        __syncthreads();
    }

    #pragma unroll
    for (int i = 0; i < 4; ++i)
        #pragma unroll
        for (int j = 0; j < 4; ++j)
            wmma::store_matrix_sync(
                out + (size_t)(m0 + wm * 64 + i * 16) * GEO_ + wn * 64 + j * 16,
                acc[i][j], GEO_, wmma::mem_row_major);
}

// ===== k_gemm_small: block 128x128, warp 32x64, 2 CTAs/SM, conflict-free pads =====
// MODE 0: A=d_S (K=256),  B=g2_w:   d_G = cnt>0 ? acc + g2b : 0
// MODE 1: A=[h|d_G] (K=2048), B=gate_w: out = sig(acc+gb)*h + (1-sig)*d_G
#define SLDA 36
#define SLDB 132
#define EPLD 68
#define SSTAGE_F (128 * SLDA + 32 * SLDB)    // 4608 + 4224 = 8832 floats
#define SMEM_SMALL (2 * SSTAGE_F * 4)        // 70656 bytes -> 2 CTAs/SM

template <int MODE>
__global__ void __launch_bounds__(256, 2) k_gemm_small(const float* __restrict__ hA,
                                                       const float* __restrict__ Bw,
                                                       const float* __restrict__ bias,
                                                       float* __restrict__ out) {
    extern __shared__ __align__(128) float sm[];
    constexpr int KTOT = (MODE == 1) ? 2 * D_ : GEO_;
    constexpr int NIT = KTOT / 32;

    const int tid = threadIdx.x;
    const int wid = tid >> 5, lane = tid & 31;
    const int wm = wid >> 1, wn = wid & 1;    // 4 x 2 warp grid, 32x64 per warp
    const int m0 = blockIdx.y * 128;
    const int n0 = blockIdx.x * 128;
    const uint32_t smb = smem_u32(sm);

    wmma::fragment<wmma::accumulator, 16, 16, 8, float> acc[2][4];
    #pragma unroll
    for (int i = 0; i < 2; ++i)
        #pragma unroll
        for (int j = 0; j < 4; ++j) wmma::fill_fragment(acc[i][j], 0.f);

    auto load_async = [&](int it, int s) {
        const int k0 = it * 32;
        const uint32_t aoff = s * SSTAGE_F;
        const uint32_t boff = s * SSTAGE_F + 128 * SLDA;
        #pragma unroll
        for (int p = 0; p < 4; ++p) {
            int idx = tid + p * 256;
            int row = idx >> 3, c4 = idx & 7;
            const float* gp;
            if (MODE == 1)
                gp = (k0 < D_) ? hA + (size_t)(m0 + row) * D_ + k0 + c4 * 4
                               : d_G + (size_t)(m0 + row) * D_ + (k0 - D_) + c4 * 4;
            else
                gp = d_S + (size_t)(m0 + row) * GEO_ + k0 + c4 * 4;
            cp16(smb + (aoff + row * SLDA + c4 * 4) * 4, gp);
        }
        #pragma unroll
        for (int p = 0; p < 4; ++p) {
            int idx = tid + p * 256;
            int row = idx >> 5, c4 = idx & 31;
            cp16(smb + (boff + row * SLDB + c4 * 4) * 4,
                 Bw + (size_t)(k0 + row) * D_ + n0 + c4 * 4);
        }
        cp_commit();
    };

    auto compute = [&](int s) {
        const float* As = sm + s * SSTAGE_F;
        const float* Bs = sm + s * SSTAGE_F + 128 * SLDA;
        #pragma unroll
        for (int ks = 0; ks < 4; ++ks) {
            wmma::fragment<wmma::matrix_a, 16, 16, 8, wmma::precision::tf32,
                           wmma::row_major> a[2];
            wmma::fragment<wmma::matrix_b, 16, 16, 8, wmma::precision::tf32,
                           wmma::row_major> b[4];
            #pragma unroll
            for (int i = 0; i < 2; ++i)
                wmma::load_matrix_sync(a[i], As + (wm * 32 + i * 16) * SLDA + ks * 8, SLDA);
            #pragma unroll
            for (int j = 0; j < 4; ++j)
                wmma::load_matrix_sync(b[j], Bs + ks * 8 * SLDB + wn * 64 + j * 16, SLDB);
            #pragma unroll
            for (int i = 0; i < 2; ++i)
                #pragma unroll
                for (int j = 0; j < 4; ++j)
                    wmma::mma_sync(acc[i][j], a[i], b[j], acc[i][j]);
        }
    };

    load_async(0, 0);
    for (int it = 0; it < NIT; ++it) {
        int cur = it & 1;
        if (it + 1 < NIT) {
            load_async(it + 1, 1 - cur);
            cp_wait<1>();
        } else {
            cp_wait<0>();
        }
        __syncthreads();
        compute(cur);
        __syncthreads();
    }

    // Epilogue via per-warp smem staging (stride 68: conflict-free)
    float* ep = sm + wid * (32 * EPLD);   // 8 * 2176 = 17408 floats <= 17664
    #pragma unroll
    for (int i = 0; i < 2; ++i)
        #pragma unroll
        for (int j = 0; j < 4; ++j)
            wmma::store_matrix_sync(ep + i * 16 * EPLD + j * 16, acc[i][j], EPLD,
                                    wmma::mem_row_major);
    __syncwarp();

    const int m = m0 + wm * 32 + lane;
    const float* row = ep + lane * EPLD;
    const int nbase = n0 + wn * 64;

    if (MODE == 1) {
        const float* hp = hA + (size_t)m * D_ + nbase;
        const float* gp = d_G + (size_t)m * D_ + nbase;
        float* op = out + (size_t)m * D_ + nbase;
        #pragma unroll
        for (int c4 = 0; c4 < 16; ++c4) {
            float4 v = *reinterpret_cast<const float4*>(row + c4 * 4);
            float4 bb = *reinterpret_cast<const float4*>(bias + nbase + c4 * 4);
            float4 hv = *reinterpret_cast<const float4*>(hp + c4 * 4);
            float4 gv = *reinterpret_cast<const float4*>(gp + c4 * 4);
            float pr[4] = {v.x + bb.x, v.y + bb.y, v.z + bb.z, v.w + bb.w};
            float hr[4] = {hv.x, hv.y, hv.z, hv.w};
            float gr[4] = {gv.x, gv.y, gv.z, gv.w};
            float4 o;
            float* opv = &o.x;
            #pragma unroll
            for (int j = 0; j < 4; ++j) {
                float alpha = 1.f / (1.f + expf(-pr[j]));
                opv[j] = alpha * hr[j] + (1.f - alpha) * gr[j];
            }
            *reinterpret_cast<float4*>(op + c4 * 4) = o;
        }
    } else {
        int l = m & (L_ - 1);
        bool on = count_of(l) > 0;
        float* gp = d_G + (size_t)m * D_ + nbase;
        #pragma unroll
        for (int c4 = 0; c4 < 16; ++c4) {
            float4 v = *reinterpret_cast<const float4*>(row + c4 * 4);
            float4 bb = *reinterpret_cast<const float4*>(bias + nbase + c4 * 4);
            float4 o;
            o.x = on ? v.x + bb.x : 0.f;
            o.y = on ? v.y + bb.y : 0.f;
            o.z = on ? v.z + bb.z : 0.f;
            o.w = on ? v.w + bb.w : 0.f;
            *reinterpret_cast<float4*>(gp + c4 * 4) = o;
        }
    }
}

extern "C" void kernel_launch(void* const* d_in, const int* in_sizes, int n_in,
                              void* d_out, int out_size) {
    const float* h   = (const float*)d_in[0];
    const float* rw  = (const float*)d_in[1];
    const float* rb  = (const float*)d_in[2];
    const float* g1w = (const float*)d_in[3];
    const float* g1b = (const float*)d_in[4];
    const float* g2w = (const float*)d_in[5];
    const float* g2b = (const float*)d_in[6];
    const float* gw  = (const float*)d_in[7];
    const float* gb  = (const float*)d_in[8];
    float* out = (float*)d_out;
    (void)in_sizes; (void)n_in; (void)out_size;

    cudaFuncSetAttribute(k_gemm_big, cudaFuncAttributeMaxDynamicSharedMemorySize, SMEM_BIG);
    cudaFuncSetAttribute(k_gemm_small<0>, cudaFuncAttributeMaxDynamicSharedMemorySize, SMEM_SMALL);
    cudaFuncSetAttribute(k_gemm_small<1>, cudaFuncAttributeMaxDynamicSharedMemorySize, SMEM_SMALL);

    float *pP, *pU, *pS, *pG1;
    cudaGetSymbolAddress((void**)&pP, d_P);
    cudaGetSymbolAddress((void**)&pU, d_U);
    cudaGetSymbolAddress((void**)&pS, d_S);
    cudaGetSymbolAddress((void**)&pG1, d_G1p);

    k_pad_g1<<<PLUP_ * GEO_ / 1024, 256>>>(g1w);
    k_z<<<BL_ / 16, 256>>>(h, rw, rb);

    // geometry path
    k_plucker<<<MROWS_ / 8, 256>>>();
    k_gemm_big<<<dim3(1, MROWS_ / 128), 256, SMEM_BIG>>>(pP, pG1, pU);
    k_reduce<<<BL_ * GEO_ / 1024, 256>>>(g1b);

    // g = S @ g2_w + b -> d_G
    k_gemm_small<0><<<dim3(D_ / 128, BL_ / 128), 256, SMEM_SMALL>>>(
        pS, g2w, g2b, nullptr);

    // gated output
    k_gemm_small<1><<<dim3(D_ / 128, BL_ / 128), 256, SMEM_SMALL>>>(
        h, gw, gb, out);
}

// round 13
// speedup vs baseline: 2.0218x; 1.9422x over previous
#include <cuda_runtime.h>
#include <math.h>
#include <stdint.h>

#define B_ 4
#define L_ 4096
#define D_ 1024
#define R_ 16
#define PLU_ 120
#define PLUP_ 128
#define GEO_ 256
#define BL_ 16384
#define MROWS_ (6 * BL_)
#define EPS_ 1e-6f

// Scratch (static device globals: allocation-free)
__device__ float d_Z[BL_ * R_];                  // (B*L, 16)
__device__ float d_S[BL_ * GEO_];                // (B*L, 256)
__device__ float d_P[(size_t)MROWS_ * PLUP_];    // plucker rows (cols 120..127 = 0)
__device__ float d_U[(size_t)MROWS_ * GEO_];     // RAW P@g1w accum (bias/gelu in reduce)
__device__ float d_G[(size_t)BL_ * D_];          // g (raw fp32)
__device__ float d_G1p[PLUP_ * GEO_];            // repacked g1_w (fragment order)
__device__ float d_W2p[GEO_ * D_];               // repacked g2_w
__device__ float d_Wgp[2 * D_ * D_];             // repacked gate_w

__constant__ int c_off[6] = {1, 2, 4, 8, 16, 32};

__device__ __forceinline__ uint32_t smem_u32(const void* p) {
    uint32_t a;
    asm("{ .reg .u64 t; cvta.to.shared.u64 t, %1; cvt.u32.u64 %0, t; }"
        : "=r"(a) : "l"(p));
    return a;
}
__device__ __forceinline__ void cp16(uint32_t s, const void* g) {
    asm volatile("cp.async.cg.shared.global [%0], [%1], 16;" :: "r"(s), "l"(g));
}
__device__ __forceinline__ void cp_commit() { asm volatile("cp.async.commit_group;"); }
template <int N>
__device__ __forceinline__ void cp_wait() {
    asm volatile("cp.async.wait_group %0;" :: "n"(N));
}
__device__ __forceinline__ void ldsm4(uint32_t* r, uint32_t addr) {
    asm volatile("ldmatrix.sync.aligned.m8n8.x4.shared.b16 {%0,%1,%2,%3}, [%4];"
                 : "=r"(r[0]), "=r"(r[1]), "=r"(r[2]), "=r"(r[3]) : "r"(addr));
}
__device__ __forceinline__ void mma_tf32(float* d, const uint32_t* a,
                                         uint32_t b0, uint32_t b1) {
    asm volatile(
        "mma.sync.aligned.m16n8k8.row.col.f32.tf32.tf32.f32 "
        "{%0,%1,%2,%3}, {%4,%5,%6,%7}, {%8,%9}, {%0,%1,%2,%3};"
        : "+f"(d[0]), "+f"(d[1]), "+f"(d[2]), "+f"(d[3])
        : "r"(a[0]), "r"(a[1]), "r"(a[2]), "r"(a[3]), "r"(b0), "r"(b1));
}
__device__ __forceinline__ float gelu_exact(float x) {
    return 0.5f * x * (1.f + erff(x * 0.7071067811865476f));
}
__device__ __forceinline__ int count_of(int l) {
    return (l >= 1) + (l >= 2) + (l >= 4) + (l >= 8) + (l >= 16) + (l >= 32);
}

// ---------------- z = h @ red_w + red_b ----------------
__global__ void k_z(const float* __restrict__ h,
                    const float* __restrict__ rw,
                    const float* __restrict__ rb) {
    int t = blockIdx.x * 16 + (threadIdx.x >> 4);
    int r = threadIdx.x & 15;
    const float* hrow = h + (size_t)t * D_;
    float acc = rb[r];
    #pragma unroll 4
    for (int d = 0; d < D_; d += 4) {
        float4 hv = *reinterpret_cast<const float4*>(hrow + d);
        acc += hv.x * rw[(d + 0) * R_ + r];
        acc += hv.y * rw[(d + 1) * R_ + r];
        acc += hv.z * rw[(d + 2) * R_ + r];
        acc += hv.w * rw[(d + 3) * R_ + r];
    }
    d_Z[t * R_ + r] = acc;
}

// ------ repack weight [K][N] -> fragment order [K/16][N/8][lane][slot] ------
// slot0: w[kb2*16 + l%4    ][nb*8 + l/4]   (b0, even k8)
// slot1: w[kb2*16 + l%4 + 4][nb*8 + l/4]   (b1, even k8)
// slot2: w[kb2*16 + 8 + l%4    ][...]      (b0, odd k8)
// slot3: w[kb2*16 + 8 + l%4 + 4][...]      (b1, odd k8)
__global__ void k_repack(const float* __restrict__ src, float* __restrict__ dst,
                         int N, int NB, int Kvalid) {
    int f = blockIdx.x * 256 + threadIdx.x;
    int s = f & 3;
    int l = (f >> 2) & 31;
    int nb = (f >> 7) % NB;
    int kb2 = f / (128 * NB);
    int k = kb2 * 16 + ((s >> 1) << 3) + (l & 3) + ((s & 1) << 2);
    int n = nb * 8 + (l >> 2);
    dst[f] = (k < Kvalid) ? src[(size_t)k * N + n] : 0.f;
}

// ---------------- plucker rows: d_P[di*BL + t][0:128] ----------------
// All shuffles warp-uniform.
__global__ void k_plucker() {
    int wid = threadIdx.x >> 5, lane = threadIdx.x & 31;
    int ridx = blockIdx.x * 8 + wid;
    int di = ridx / BL_;
    int t = ridx - di * BL_;
    int l = t & (L_ - 1);
    int delta = c_off[di];
    float* dst = d_P + (size_t)ridx * PLUP_;
    if (l < delta) {                       // warp-uniform branch
        #pragma unroll
        for (int q = 0; q < 4; ++q) dst[lane + q * 32] = 0.f;
        return;
    }
    int tp = t - delta;
    float w = (lane < 16) ? d_Z[tp * R_ + lane] : d_Z[t * R_ + lane - 16];
    float p[4];
    float sq = 0.f;
    #pragma unroll
    for (int q = 0; q < 4; ++q) {
        int k = lane + q * 32;
        int kc = (k < PLU_) ? k : 0;
        int kk = kc, i = 0, len = R_ - 1;
        while (kk >= len) { kk -= len; i++; len--; }
        int j = i + 1 + kk;
        float ui = __shfl_sync(0xffffffffu, w, i);
        float uj = __shfl_sync(0xffffffffu, w, j);
        float vi = __shfl_sync(0xffffffffu, w, 16 + i);
        float vj = __shfl_sync(0xffffffffu, w, 16 + j);
        float val = (k < PLU_) ? (ui * vj - uj * vi) : 0.f;
        p[q] = val;
        sq += val * val;
    }
    #pragma unroll
    for (int o = 16; o > 0; o >>= 1) sq += __shfl_xor_sync(0xffffffffu, sq, o);
    float inv = 1.f / fmaxf(sqrtf(sq), EPS_);
    #pragma unroll
    for (int q = 0; q < 4; ++q) dst[lane + q * 32] = p[q] * inv;
}

// -------- reduce: d_S = (sum masked gelu(d_U + g1b))/cnt ----------------
__global__ void k_reduce(const float* __restrict__ g1b) {
    int fid = blockIdx.x * 256 + threadIdx.x;   // BL*GEO/4 float4s
    int t = fid >> 6;
    int c = (fid & 63) * 4;
    int l = t & (L_ - 1);
    float4 bb = *reinterpret_cast<const float4*>(g1b + c);
    float4 s = make_float4(0.f, 0.f, 0.f, 0.f);
    #pragma unroll
    for (int di = 0; di < 6; ++di) {
        if (l >= c_off[di]) {
            float4 u = *reinterpret_cast<const float4*>(
                d_U + (size_t)(di * BL_ + t) * GEO_ + c);
            s.x += gelu_exact(u.x + bb.x);
            s.y += gelu_exact(u.y + bb.y);
            s.z += gelu_exact(u.z + bb.z);
            s.w += gelu_exact(u.w + bb.w);
        }
    }
    int cnt = count_of(l);
    float sc = cnt > 0 ? 1.f / (float)cnt : 0.f;
    s.x *= sc; s.y *= sc; s.z *= sc; s.w *= sc;
    *reinterpret_cast<float4*>(d_S + (size_t)t * GEO_ + c) = s;
}

// ====== explicit-mma tf32 GEMM: block 128x128, warp 32x64, 2 CTAs/SM ======
// MODE 0: A=d_S (K=256),  B=d_W2p:  d_G = cnt>0 ? acc + g2b : 0
// MODE 1: A=[h|d_G] (K=2048), B=d_Wgp: out = sig(acc+gb)*h + (1-sig)*d_G
// MODE 2: A=d_P (K=128),  B=d_G1p (NG=256): d_U = raw acc
#define SLDA 36
#define AFLOATS (128 * SLDA)              // 4608
#define BFLOATS 4096                      // 2 slices x 16 nb x 128
#define SSTAGE_F (AFLOATS + BFLOATS)      // 8704 floats
#define SMEM_GEMM (2 * SSTAGE_F * 4)      // 69632 bytes -> 2 CTAs/SM
#define EPLD 68

template <int MODE>
__global__ void __launch_bounds__(256, 2) k_gemm(const float* __restrict__ hA,
                                                 const float* __restrict__ Bp,
                                                 const float* __restrict__ bias,
                                                 float* __restrict__ out) {
    extern __shared__ __align__(128) float sm[];
    constexpr int KTOT = (MODE == 1) ? 2 * D_ : (MODE == 0 ? GEO_ : PLUP_);
    constexpr int NG = (MODE == 2) ? GEO_ : D_;
    constexpr int NB = NG / 8;
    constexpr int NIT = KTOT / 32;

    const int tid = threadIdx.x;
    const int wid = tid >> 5, lane = tid & 31;
    const int wm = wid >> 1, wn = wid & 1;    // 4 x 2 warp grid, 32x64 per warp
    const int m0 = blockIdx.y * 128;
    const int n0 = blockIdx.x * 128;
    const uint32_t smb = smem_u32(sm);

    // ldmatrix lane address components (A-tile row/col units)
    const int lrow = (lane & 7) + ((lane >> 3) & 1) * 8;
    const int lcol = (lane >> 4) * 4;

    float acc[2][8][4];
    #pragma unroll
    for (int i = 0; i < 2; ++i)
        #pragma unroll
        for (int nb = 0; nb < 8; ++nb)
            #pragma unroll
            for (int q = 0; q < 4; ++q) acc[i][nb][q] = 0.f;

    auto load_async = [&](int it, int s) {
        const int k0 = it * 32;
        const uint32_t aoff = s * SSTAGE_F;
        const uint32_t boff = s * SSTAGE_F + AFLOATS;
        // A: 128 rows x 32 floats, row-major padded
        #pragma unroll
        for (int p = 0; p < 4; ++p) {
            int idx = tid + p * 256;
            int row = idx >> 3, c4 = idx & 7;
            const float* gp;
            if (MODE == 1)
                gp = (k0 < D_) ? hA + (size_t)(m0 + row) * D_ + k0 + c4 * 4
                               : d_G + (size_t)(m0 + row) * D_ + (k0 - D_) + c4 * 4;
            else if (MODE == 0)
                gp = d_S + (size_t)(m0 + row) * GEO_ + k0 + c4 * 4;
            else
                gp = d_P + (size_t)(m0 + row) * PLUP_ + k0 + c4 * 4;
            cp16(smb + (aoff + row * SLDA + c4 * 4) * 4, gp);
        }
        // B: repacked, 1024 float4 linear (2 k16-slices x 16 nb x 128 floats)
        const float* bsrc = Bp + ((size_t)(k0 >> 4) * NB + (n0 >> 3)) * 128;
        #pragma unroll
        for (int p = 0; p < 4; ++p) {
            int idx = tid + p * 256;    // float4 index
            int slice = idx >> 9;
            int pos = idx & 511;
            cp16(smb + (boff + idx * 4) * 4,
                 bsrc + (size_t)slice * NB * 128 + pos * 4);
        }
        cp_commit();
    };

    auto compute = [&](int s) {
        const float* Bs = sm + s * SSTAGE_F + AFLOATS;
        const uint32_t abase = smb + (s * SSTAGE_F) * 4;
        #pragma unroll
        for (int kb2s = 0; kb2s < 2; ++kb2s) {
            uint32_t a[2][2][4];
            #pragma unroll
            for (int i = 0; i < 2; ++i)
                #pragma unroll
                for (int kss = 0; kss < 2; ++kss) {
                    int ks = kb2s * 2 + kss;
                    ldsm4(a[i][kss],
                          abase + ((wm * 32 + i * 16 + lrow) * SLDA + ks * 8 + lcol) * 4);
                }
            #pragma unroll
            for (int nb = 0; nb < 8; ++nb) {
                float4 b4 = *reinterpret_cast<const float4*>(
                    Bs + kb2s * 2048 + (wn * 8 + nb) * 128 + lane * 4);
                uint32_t b0 = __float_as_uint(b4.x), b1 = __float_as_uint(b4.y);
                uint32_t b2 = __float_as_uint(b4.z), b3 = __float_as_uint(b4.w);
                #pragma unroll
                for (int i = 0; i < 2; ++i) {
                    mma_tf32(acc[i][nb], a[i][0], b0, b1);
                    mma_tf32(acc[i][nb], a[i][1], b2, b3);
                }
            }
        }
    };

    load_async(0, 0);
    for (int it = 0; it < NIT; ++it) {
        int cur = it & 1;
        if (it + 1 < NIT) {
            load_async(it + 1, 1 - cur);
            cp_wait<1>();
        } else {
            cp_wait<0>();
        }
        __syncthreads();
        compute(cur);
        __syncthreads();
    }

    // Stage accumulators to per-warp smem (overlaps stage buffers: synced above)
    float* ep = sm + wid * (32 * EPLD);
    const int g = lane >> 2, t4 = lane & 3;
    #pragma unroll
    for (int i = 0; i < 2; ++i)
        #pragma unroll
        for (int nb = 0; nb < 8; ++nb) {
            *reinterpret_cast<float2*>(ep + (i * 16 + g) * EPLD + nb * 8 + 2 * t4) =
                make_float2(acc[i][nb][0], acc[i][nb][1]);
            *reinterpret_cast<float2*>(ep + (i * 16 + g + 8) * EPLD + nb * 8 + 2 * t4) =
                make_float2(acc[i][nb][2], acc[i][nb][3]);
        }
    __syncwarp();

    const int m = m0 + wm * 32 + lane;
    const float* row = ep + lane * EPLD;
    const int nbase = n0 + wn * 64;

    if (MODE == 1) {
        const float* hp = hA + (size_t)m * D_ + nbase;
        const float* gp = d_G + (size_t)m * D_ + nbase;
        float* op = out + (size_t)m * D_ + nbase;
        #pragma unroll
        for (int c4 = 0; c4 < 16; ++c4) {
            float4 v = *reinterpret_cast<const float4*>(row + c4 * 4);
            float4 bb = *reinterpret_cast<const float4*>(bias + nbase + c4 * 4);
            float4 hv = *reinterpret_cast<const float4*>(hp + c4 * 4);
            float4 gv = *reinterpret_cast<const float4*>(gp + c4 * 4);
            float pr[4] = {v.x + bb.x, v.y + bb.y, v.z + bb.z, v.w + bb.w};
            float hr[4] = {hv.x, hv.y, hv.z, hv.w};
            float gr[4] = {gv.x, gv.y, gv.z, gv.w};
            float4 o;
            float* opv = &o.x;
            #pragma unroll
            for (int j = 0; j < 4; ++j) {
                float alpha = 1.f / (1.f + expf(-pr[j]));
                opv[j] = alpha * hr[j] + (1.f - alpha) * gr[j];
            }
            *reinterpret_cast<float4*>(op + c4 * 4) = o;
        }
    } else if (MODE == 0) {
        int l = m & (L_ - 1);
        bool on = count_of(l) > 0;
        float* gp = d_G + (size_t)m * D_ + nbase;
        #pragma unroll
        for (int c4 = 0; c4 < 16; ++c4) {
            float4 v = *reinterpret_cast<const float4*>(row + c4 * 4);
            float4 bb = *reinterpret_cast<const float4*>(bias + nbase + c4 * 4);
            float4 o;
            o.x = on ? v.x + bb.x : 0.f;
            o.y = on ? v.y + bb.y : 0.f;
            o.z = on ? v.z + bb.z : 0.f;
            o.w = on ? v.w + bb.w : 0.f;
            *reinterpret_cast<float4*>(gp + c4 * 4) = o;
        }
    } else {
        float* up = out + (size_t)m * GEO_ + nbase;
        #pragma unroll
        for (int c4 = 0; c4 < 16; ++c4)
            *reinterpret_cast<float4*>(up + c4 * 4) =
                *reinterpret_cast<const float4*>(row + c4 * 4);
    }
}

extern "C" void kernel_launch(void* const* d_in, const int* in_sizes, int n_in,
                              void* d_out, int out_size) {
    const float* h   = (const float*)d_in[0];
    const float* rw  = (const float*)d_in[1];
    const float* rb  = (const float*)d_in[2];
    const float* g1w = (const float*)d_in[3];
    const float* g1b = (const float*)d_in[4];
    const float* g2w = (const float*)d_in[5];
    const float* g2b = (const float*)d_in[6];
    const float* gw  = (const float*)d_in[7];
    const float* gb  = (const float*)d_in[8];
    float* out = (float*)d_out;
    (void)in_sizes; (void)n_in; (void)out_size;

    cudaFuncSetAttribute(k_gemm<0>, cudaFuncAttributeMaxDynamicSharedMemorySize, SMEM_GEMM);
    cudaFuncSetAttribute(k_gemm<1>, cudaFuncAttributeMaxDynamicSharedMemorySize, SMEM_GEMM);
    cudaFuncSetAttribute(k_gemm<2>, cudaFuncAttributeMaxDynamicSharedMemorySize, SMEM_GEMM);

    float *pP, *pU, *pS, *pG1, *pW2, *pWg;
    cudaGetSymbolAddress((void**)&pP, d_P);
    cudaGetSymbolAddress((void**)&pU, d_U);
    cudaGetSymbolAddress((void**)&pS, d_S);
    cudaGetSymbolAddress((void**)&pG1, d_G1p);
    cudaGetSymbolAddress((void**)&pW2, d_W2p);
    cudaGetSymbolAddress((void**)&pWg, d_Wgp);

    // weight repacks (fragment order)
    k_repack<<<PLUP_ * GEO_ / 256, 256>>>(g1w, pG1, GEO_, GEO_ / 8, PLU_);
    k_repack<<<GEO_ * D_ / 256, 256>>>(g2w, pW2, D_, D_ / 8, GEO_);
    k_repack<<<2 * D_ * D_ / 256, 256>>>(gw, pWg, D_, D_ / 8, 2 * D_);

    k_z<<<BL_ / 16, 256>>>(h, rw, rb);

    // geometry path
    k_plucker<<<MROWS_ / 8, 256>>>();
    k_gemm<2><<<dim3(GEO_ / 128, MROWS_ / 128), 256, SMEM_GEMM>>>(pP, pG1, nullptr, pU);
    k_reduce<<<BL_ * GEO_ / 1024, 256>>>(g1b);

    // g = S @ g2_w + b -> d_G
    k_gemm<0><<<dim3(D_ / 128, BL_ / 128), 256, SMEM_GEMM>>>(pS, pW2, g2b, nullptr);

    // gated output
    k_gemm<1><<<dim3(D_ / 128, BL_ / 128), 256, SMEM_GEMM>>>(h, pWg, gb, out);
}

// round 14
// speedup vs baseline: 2.1750x; 1.0758x over previous
#include <cuda_runtime.h>
#include <math.h>
#include <stdint.h>

#define B_ 4
#define L_ 4096
#define D_ 1024
#define R_ 16
#define PLU_ 120
#define PLUP_ 128
#define GEO_ 256
#define BL_ 16384
#define MROWS_ (6 * BL_)
#define EPS_ 1e-6f

// Scratch (static device globals: allocation-free)
__device__ float d_Z[BL_ * R_];                  // (B*L, 16)
__device__ float d_S[BL_ * GEO_];                // (B*L, 256): atomic gelu-sum
__device__ float d_P[(size_t)MROWS_ * PLUP_];    // plucker rows (cols 120..127 = 0)
__device__ float d_G[(size_t)BL_ * D_];          // g (raw fp32)
__device__ float d_G1p[PLUP_ * GEO_];            // repacked g1_w (fragment order)
__device__ float d_W2p[GEO_ * D_];               // repacked g2_w
__device__ float d_Wgp[2 * D_ * D_];             // repacked gate_w
__device__ float d_RwT[R_ * D_];                 // red_w transposed [16][1024]

__constant__ int c_off[6] = {1, 2, 4, 8, 16, 32};

__device__ __forceinline__ uint32_t smem_u32(const void* p) {
    uint32_t a;
    asm("{ .reg .u64 t; cvta.to.shared.u64 t, %1; cvt.u32.u64 %0, t; }"
        : "=r"(a) : "l"(p));
    return a;
}
__device__ __forceinline__ void cp16(uint32_t s, const void* g) {
    asm volatile("cp.async.cg.shared.global [%0], [%1], 16;" :: "r"(s), "l"(g));
}
__device__ __forceinline__ void cp_commit() { asm volatile("cp.async.commit_group;"); }
template <int N>
__device__ __forceinline__ void cp_wait() {
    asm volatile("cp.async.wait_group %0;" :: "n"(N));
}
__device__ __forceinline__ void ldsm4(uint32_t* r, uint32_t addr) {
    asm volatile("ldmatrix.sync.aligned.m8n8.x4.shared.b16 {%0,%1,%2,%3}, [%4];"
                 : "=r"(r[0]), "=r"(r[1]), "=r"(r[2]), "=r"(r[3]) : "r"(addr));
}
__device__ __forceinline__ void mma_tf32(float* d, const uint32_t* a,
                                         uint32_t b0, uint32_t b1) {
    asm volatile(
        "mma.sync.aligned.m16n8k8.row.col.f32.tf32.tf32.f32 "
        "{%0,%1,%2,%3}, {%4,%5,%6,%7}, {%8,%9}, {%0,%1,%2,%3};"
        : "+f"(d[0]), "+f"(d[1]), "+f"(d[2]), "+f"(d[3])
        : "r"(a[0]), "r"(a[1]), "r"(a[2]), "r"(a[3]), "r"(b0), "r"(b1));
}
__device__ __forceinline__ float gelu_exact(float x) {
    return 0.5f * x * (1.f + erff(x * 0.7071067811865476f));
}
__device__ __forceinline__ int count_of(int l) {
    return (l >= 1) + (l >= 2) + (l >= 4) + (l >= 8) + (l >= 16) + (l >= 32);
}

// ---------------- transpose red_w -> d_RwT[16][1024] ----------------
__global__ void k_rwT(const float* __restrict__ rw) {
    int i = blockIdx.x * 256 + threadIdx.x;   // 16384
    int d = i >> 4, r = i & 15;
    d_RwT[r * D_ + d] = rw[d * R_ + r];
}

// ---------------- z = h @ red_w + red_b (warp per token) ----------------
__global__ void k_z2(const float* __restrict__ h, const float* __restrict__ rb) {
    extern __shared__ float rwT[];            // 64KB
    int tid = threadIdx.x, wid = tid >> 5, lane = tid & 31;
    for (int i = tid * 4; i < R_ * D_; i += 1024)
        *reinterpret_cast<float4*>(rwT + i) =
            *reinterpret_cast<const float4*>(d_RwT + i);
    __syncthreads();

    int t = blockIdx.x * 8 + wid;
    float acc[16];
    #pragma unroll
    for (int r = 0; r < 16; ++r) acc[r] = 0.f;
    const float* hrow = h + (size_t)t * D_;
    #pragma unroll
    for (int it = 0; it < 8; ++it) {
        float4 hv = *reinterpret_cast<const float4*>(hrow + it * 128 + lane * 4);
        #pragma unroll
        for (int r = 0; r < 16; ++r) {
            float4 wv = *reinterpret_cast<const float4*>(
                rwT + r * D_ + it * 128 + lane * 4);
            acc[r] += hv.x * wv.x + hv.y * wv.y + hv.z * wv.z + hv.w * wv.w;
        }
    }
    #pragma unroll
    for (int r = 0; r < 16; ++r)
        #pragma unroll
        for (int o = 16; o > 0; o >>= 1)
            acc[r] += __shfl_xor_sync(0xffffffffu, acc[r], o);
    if (lane == 0) {
        #pragma unroll
        for (int r = 0; r < 16; ++r) d_Z[t * R_ + r] = acc[r] + rb[r];
    }
}

// ---------------- zero d_S ----------------
__global__ void k_zeroS() {
    int i = blockIdx.x * 256 + threadIdx.x;
    *reinterpret_cast<float4*>(d_S + (size_t)i * 4) = make_float4(0.f, 0.f, 0.f, 0.f);
}

// ------ repack weight [K][N] -> fragment order [K/16][N/8][lane][slot] ------
// Tiled: coalesced reads -> smem -> coalesced writes.
__global__ void k_repack(const float* __restrict__ src, float* __restrict__ dst,
                         int N, int NB, int Kvalid) {
    __shared__ float tile[16 * 132];
    int tid = threadIdx.x;
    int k0 = blockIdx.y * 16;
    int n0 = blockIdx.x * 128;
    #pragma unroll
    for (int p = 0; p < 8; ++p) {
        int idx = tid + p * 256;              // 2048 = 16 x 128
        int kr = idx >> 7, nn = idx & 127;
        tile[kr * 132 + nn] = (k0 + kr < Kvalid)
            ? src[(size_t)(k0 + kr) * N + n0 + nn] : 0.f;
    }
    __syncthreads();
    size_t base = ((size_t)blockIdx.y * NB + (n0 >> 3)) * 128;
    #pragma unroll
    for (int p = 0; p < 8; ++p) {
        int idx = tid + p * 256;              // local dst offset
        int s = idx & 3;
        int l = (idx >> 2) & 31;
        int nbL = idx >> 7;
        int kr = ((s >> 1) << 3) + (l & 3) + ((s & 1) << 2);
        int nn = nbL * 8 + (l >> 2);
        dst[base + idx] = tile[kr * 132 + nn];
    }
}

// ---------------- plucker rows: d_P[di*BL + t][0:128] ----------------
// All shuffles warp-uniform.
__global__ void k_plucker() {
    int wid = threadIdx.x >> 5, lane = threadIdx.x & 31;
    int ridx = blockIdx.x * 8 + wid;
    int di = ridx / BL_;
    int t = ridx - di * BL_;
    int l = t & (L_ - 1);
    int delta = c_off[di];
    float* dst = d_P + (size_t)ridx * PLUP_;
    if (l < delta) {                       // warp-uniform branch
        #pragma unroll
        for (int q = 0; q < 4; ++q) dst[lane + q * 32] = 0.f;
        return;
    }
    int tp = t - delta;
    float w = (lane < 16) ? d_Z[tp * R_ + lane] : d_Z[t * R_ + lane - 16];
    float p[4];
    float sq = 0.f;
    #pragma unroll
    for (int q = 0; q < 4; ++q) {
        int k = lane + q * 32;
        int kc = (k < PLU_) ? k : 0;
        int kk = kc, i = 0, len = R_ - 1;
        while (kk >= len) { kk -= len; i++; len--; }
        int j = i + 1 + kk;
        float ui = __shfl_sync(0xffffffffu, w, i);
        float uj = __shfl_sync(0xffffffffu, w, j);
        float vi = __shfl_sync(0xffffffffu, w, 16 + i);
        float vj = __shfl_sync(0xffffffffu, w, 16 + j);
        float val = (k < PLU_) ? (ui * vj - uj * vi) : 0.f;
        p[q] = val;
        sq += val * val;
    }
    #pragma unroll
    for (int o = 16; o > 0; o >>= 1) sq += __shfl_xor_sync(0xffffffffu, sq, o);
    float inv = 1.f / fmaxf(sqrtf(sq), EPS_);
    #pragma unroll
    for (int q = 0; q < 4; ++q) dst[lane + q * 32] = p[q] * inv;
}

// ====== explicit-mma tf32 GEMM: block 128x128, warp 32x64, 2 CTAs/SM ======
// MODE 0: A=d_S (K=256),  B=d_W2p:  d_G = cnt>0 ? acc/cnt + g2b : 0
// MODE 1: A=[h|d_G] (K=2048), B=d_Wgp: out = sig(acc+gb)*h + (1-sig)*d_G
// MODE 2: A=d_P (K=128),  B=d_G1p (NG=256): atomicAdd(d_S, masked gelu(acc+g1b))
#define SLDA 36
#define AFLOATS (128 * SLDA)              // 4608
#define BFLOATS 4096                      // 2 slices x 16 nb x 128
#define SSTAGE_F (AFLOATS + BFLOATS)      // 8704 floats
#define SMEM_GEMM (2 * SSTAGE_F * 4)      // 69632 bytes -> 2 CTAs/SM
#define EPLD 68

template <int MODE>
__global__ void __launch_bounds__(256, 2) k_gemm(const float* __restrict__ hA,
                                                 const float* __restrict__ Bp,
                                                 const float* __restrict__ bias,
                                                 float* __restrict__ out) {
    extern __shared__ __align__(128) float sm[];
    constexpr int KTOT = (MODE == 1) ? 2 * D_ : (MODE == 0 ? GEO_ : PLUP_);
    constexpr int NG = (MODE == 2) ? GEO_ : D_;
    constexpr int NB = NG / 8;
    constexpr int NIT = KTOT / 32;

    const int tid = threadIdx.x;
    const int wid = tid >> 5, lane = tid & 31;
    const int wm = wid >> 1, wn = wid & 1;    // 4 x 2 warp grid, 32x64 per warp
    const int m0 = blockIdx.y * 128;
    const int n0 = blockIdx.x * 128;
    const uint32_t smb = smem_u32(sm);

    // ldmatrix lane address components (A-tile row/col units)
    const int lrow = (lane & 7) + ((lane >> 3) & 1) * 8;
    const int lcol = (lane >> 4) * 4;

    float acc[2][8][4];
    #pragma unroll
    for (int i = 0; i < 2; ++i)
        #pragma unroll
        for (int nb = 0; nb < 8; ++nb)
            #pragma unroll
            for (int q = 0; q < 4; ++q) acc[i][nb][q] = 0.f;

    auto load_async = [&](int it, int s) {
        const int k0 = it * 32;
        const uint32_t aoff = s * SSTAGE_F;
        const uint32_t boff = s * SSTAGE_F + AFLOATS;
        #pragma unroll
        for (int p = 0; p < 4; ++p) {
            int idx = tid + p * 256;
            int row = idx >> 3, c4 = idx & 7;
            const float* gp;
            if (MODE == 1)
                gp = (k0 < D_) ? hA + (size_t)(m0 + row) * D_ + k0 + c4 * 4
                               : d_G + (size_t)(m0 + row) * D_ + (k0 - D_) + c4 * 4;
            else if (MODE == 0)
                gp = d_S + (size_t)(m0 + row) * GEO_ + k0 + c4 * 4;
            else
                gp = d_P + (size_t)(m0 + row) * PLUP_ + k0 + c4 * 4;
            cp16(smb + (aoff + row * SLDA + c4 * 4) * 4, gp);
        }
        const float* bsrc = Bp + ((size_t)(k0 >> 4) * NB + (n0 >> 3)) * 128;
        #pragma unroll
        for (int p = 0; p < 4; ++p) {
            int idx = tid + p * 256;    // float4 index
            int slice = idx >> 9;
            int pos = idx & 511;
            cp16(smb + (boff + idx * 4) * 4,
                 bsrc + (size_t)slice * NB * 128 + pos * 4);
        }
        cp_commit();
    };

    auto compute = [&](int s) {
        const float* Bs = sm + s * SSTAGE_F + AFLOATS;
        const uint32_t abase = smb + (s * SSTAGE_F) * 4;
        #pragma unroll
        for (int kb2s = 0; kb2s < 2; ++kb2s) {
            uint32_t a[2][2][4];
            #pragma unroll
            for (int i = 0; i < 2; ++i)
                #pragma unroll
                for (int kss = 0; kss < 2; ++kss) {
                    int ks = kb2s * 2 + kss;
                    ldsm4(a[i][kss],
                          abase + ((wm * 32 + i * 16 + lrow) * SLDA + ks * 8 + lcol) * 4);
                }
            #pragma unroll
            for (int nb = 0; nb < 8; ++nb) {
                float4 b4 = *reinterpret_cast<const float4*>(
                    Bs + kb2s * 2048 + (wn * 8 + nb) * 128 + lane * 4);
                uint32_t b0 = __float_as_uint(b4.x), b1 = __float_as_uint(b4.y);
                uint32_t b2 = __float_as_uint(b4.z), b3 = __float_as_uint(b4.w);
                #pragma unroll
                for (int i = 0; i < 2; ++i) {
                    mma_tf32(acc[i][nb], a[i][0], b0, b1);
                    mma_tf32(acc[i][nb], a[i][1], b2, b3);
                }
            }
        }
    };

    load_async(0, 0);
    for (int it = 0; it < NIT; ++it) {
        int cur = it & 1;
        if (it + 1 < NIT) {
            load_async(it + 1, 1 - cur);
            cp_wait<1>();
        } else {
            cp_wait<0>();
        }
        __syncthreads();
        compute(cur);
        __syncthreads();
    }

    if (MODE == 2) {
        // Direct from regs: masked gelu(acc + g1b) atomically into d_S[t][n].
        const int g = lane >> 2, t4 = lane & 3;
        #pragma unroll
        for (int i = 0; i < 2; ++i) {
            #pragma unroll
            for (int half = 0; half < 2; ++half) {
                int mrow = m0 + wm * 32 + i * 16 + g + half * 8;
                int di = mrow / BL_;
                int t = mrow - di * BL_;
                int l = t & (L_ - 1);
                bool on = l >= c_off[di];
                float* srow = d_S + (size_t)t * GEO_;
                if (on) {
                    #pragma unroll
                    for (int nb = 0; nb < 8; ++nb) {
                        int n = n0 + wn * 64 + nb * 8 + t4 * 2;
                        atomicAdd(srow + n,
                                  gelu_exact(acc[i][nb][half * 2 + 0] + bias[n]));
                        atomicAdd(srow + n + 1,
                                  gelu_exact(acc[i][nb][half * 2 + 1] + bias[n + 1]));
                    }
                }
            }
        }
        return;
    }

    // Stage accumulators to per-warp smem
    float* ep = sm + wid * (32 * EPLD);
    const int g = lane >> 2, t4 = lane & 3;
    #pragma unroll
    for (int i = 0; i < 2; ++i)
        #pragma unroll
        for (int nb = 0; nb < 8; ++nb) {
            *reinterpret_cast<float2*>(ep + (i * 16 + g) * EPLD + nb * 8 + 2 * t4) =
                make_float2(acc[i][nb][0], acc[i][nb][1]);
            *reinterpret_cast<float2*>(ep + (i * 16 + g + 8) * EPLD + nb * 8 + 2 * t4) =
                make_float2(acc[i][nb][2], acc[i][nb][3]);
        }
    __syncwarp();

    const int m = m0 + wm * 32 + lane;
    const float* row = ep + lane * EPLD;
    const int nbase = n0 + wn * 64;

    if (MODE == 1) {
        const float* hp = hA + (size_t)m * D_ + nbase;
        const float* gp = d_G + (size_t)m * D_ + nbase;
        float* op = out + (size_t)m * D_ + nbase;
        #pragma unroll
        for (int c4 = 0; c4 < 16; ++c4) {
            float4 v = *reinterpret_cast<const float4*>(row + c4 * 4);
            float4 bb = *reinterpret_cast<const float4*>(bias + nbase + c4 * 4);
            float4 hv = *reinterpret_cast<const float4*>(hp + c4 * 4);
            float4 gv = *reinterpret_cast<const float4*>(gp + c4 * 4);
            float pr[4] = {v.x + bb.x, v.y + bb.y, v.z + bb.z, v.w + bb.w};
            float hr[4] = {hv.x, hv.y, hv.z, hv.w};
            float gr[4] = {gv.x, gv.y, gv.z, gv.w};
            float4 o;
            float* opv = &o.x;
            #pragma unroll
            for (int j = 0; j < 4; ++j) {
                float alpha = 1.f / (1.f + expf(-pr[j]));
                opv[j] = alpha * hr[j] + (1.f - alpha) * gr[j];
            }
            *reinterpret_cast<float4*>(op + c4 * 4) = o;
        }
    } else {   // MODE 0: divide by count here ((Σu)@W / c == (Σu/c)@W)
        int l = m & (L_ - 1);
        int cnt = count_of(l);
        float sc = cnt > 0 ? 1.f / (float)cnt : 0.f;
        bool on = cnt > 0;
        float* gp = d_G + (size_t)m * D_ + nbase;
        #pragma unroll
        for (int c4 = 0; c4 < 16; ++c4) {
            float4 v = *reinterpret_cast<const float4*>(row + c4 * 4);
            float4 bb = *reinterpret_cast<const float4*>(bias + nbase + c4 * 4);
            float4 o;
            o.x = on ? v.x * sc + bb.x : 0.f;
            o.y = on ? v.y * sc + bb.y : 0.f;
            o.z = on ? v.z * sc + bb.z : 0.f;
            o.w = on ? v.w * sc + bb.w : 0.f;
            *reinterpret_cast<float4*>(gp + c4 * 4) = o;
        }
    }
}

extern "C" void kernel_launch(void* const* d_in, const int* in_sizes, int n_in,
                              void* d_out, int out_size) {
    const float* h   = (const float*)d_in[0];
    const float* rw  = (const float*)d_in[1];
    const float* rb  = (const float*)d_in[2];
    const float* g1w = (const float*)d_in[3];
    const float* g1b = (const float*)d_in[4];
    const float* g2w = (const float*)d_in[5];
    const float* g2b = (const float*)d_in[6];
    const float* gw  = (const float*)d_in[7];
    const float* gb  = (const float*)d_in[8];
    float* out = (float*)d_out;
    (void)in_sizes; (void)n_in; (void)out_size;

    cudaFuncSetAttribute(k_gemm<0>, cudaFuncAttributeMaxDynamicSharedMemorySize, SMEM_GEMM);
    cudaFuncSetAttribute(k_gemm<1>, cudaFuncAttributeMaxDynamicSharedMemorySize, SMEM_GEMM);
    cudaFuncSetAttribute(k_gemm<2>, cudaFuncAttributeMaxDynamicSharedMemorySize, SMEM_GEMM);
    cudaFuncSetAttribute(k_z2, cudaFuncAttributeMaxDynamicSharedMemorySize,
                         R_ * D_ * (int)sizeof(float));

    float *pP, *pS, *pG1, *pW2, *pWg;
    cudaGetSymbolAddress((void**)&pP, d_P);
    cudaGetSymbolAddress((void**)&pS, d_S);
    cudaGetSymbolAddress((void**)&pG1, d_G1p);
    cudaGetSymbolAddress((void**)&pW2, d_W2p);
    cudaGetSymbolAddress((void**)&pWg, d_Wgp);

    // weight prep
    k_rwT<<<R_ * D_ / 256, 256>>>(rw);
    k_repack<<<dim3(GEO_ / 128, PLUP_ / 16), 256>>>(g1w, pG1, GEO_, GEO_ / 8, PLU_);
    k_repack<<<dim3(D_ / 128, GEO_ / 16), 256>>>(g2w, pW2, D_, D_ / 8, GEO_);
    k_repack<<<dim3(D_ / 128, 2 * D_ / 16), 256>>>(gw, pWg, D_, D_ / 8, 2 * D_);

    k_z2<<<BL_ / 8, 256, R_ * D_ * sizeof(float)>>>(h, rb);
    k_zeroS<<<BL_ * GEO_ / 1024, 256>>>();

    // geometry path: plucker -> GEMM with fused gelu+mask+atomic-reduce into d_S
    k_plucker<<<MROWS_ / 8, 256>>>();
    k_gemm<2><<<dim3(GEO_ / 128, MROWS_ / 128), 256, SMEM_GEMM>>>(pP, pG1, g1b, nullptr);

    // g = (d_S/cnt) @ g2_w + b -> d_G   (division folded into epilogue)
    k_gemm<0><<<dim3(D_ / 128, BL_ / 128), 256, SMEM_GEMM>>>(pS, pW2, g2b, nullptr);

    // gated output
    k_gemm<1><<<dim3(D_ / 128, BL_ / 128), 256, SMEM_GEMM>>>(h, pWg, gb, out);
}